// round 8
// baseline (speedup 1.0000x reference)
#include <cuda_runtime.h>
#include <cuda_bf16.h>
#include <math.h>
#include <stdint.h>

#define B_ 32
#define T_ 512
#define D_ 1024
#define H_ 1024
#define ZN 4096
#define NBLK 128

// ---------------- device scratch ----------------
__device__ float g_G[(size_t)T_ * B_ * ZN];       // 256MB: x@Wx + bias, row r = t*32+b (reversed time)
__device__ float g_Ap[(size_t)128 * 32 * 4096];   // 64MB: repacked x (tf32, kperm, tiled 128x32)
__device__ float g_Bp[(size_t)32 * 32 * 4096];    // 16MB: repacked Wx (tf32, kperm, tiled 128x32)
__device__ float g_h[2][H_ * B_];                 // double-buffered h, mma-fragment-packed
__device__ unsigned g_flags[NBLK * 32];           // per-block progress flags, 128B apart
__device__ unsigned g_done = 0;

// ---------------- helpers ----------------
__device__ __forceinline__ float sigf(float x) { return 1.0f / (1.0f + __expf(-x)); }

__device__ __forceinline__ uint32_t f2tf32(float x) {
    uint32_t u;
    asm("cvt.rna.tf32.f32 %0, %1;" : "=r"(u) : "f"(x));
    return u;
}

__device__ __forceinline__ void mma_m16n8k8(float* c, const uint32_t* a, uint32_t b0, uint32_t b1) {
    asm volatile(
        "mma.sync.aligned.m16n8k8.row.col.f32.tf32.tf32.f32 "
        "{%0,%1,%2,%3}, {%4,%5,%6,%7}, {%8,%9}, {%0,%1,%2,%3};"
        : "+f"(c[0]), "+f"(c[1]), "+f"(c[2]), "+f"(c[3])
        : "r"(a[0]), "r"(a[1]), "r"(a[2]), "r"(a[3]), "r"(b0), "r"(b1));
}

// k-permute within an 8-chunk so frag pairs (k, k+4) are adjacent words (LDS.64)
__device__ __forceinline__ int kperm(int r) { return ((r & 3) << 1) | (r >> 2); }

__device__ __forceinline__ void cpa16(float* dst, const float* src) {
    unsigned s = (unsigned)__cvta_generic_to_shared(dst);
    asm volatile("cp.async.cg.shared.global [%0], [%1], 16;" :: "r"(s), "l"(src));
}

__device__ __forceinline__ unsigned ld_acq(const unsigned* p) {
    unsigned v;
    asm volatile("ld.global.acquire.gpu.u32 %0, [%1];" : "=r"(v) : "l"(p) : "memory");
    return v;
}
__device__ __forceinline__ void st_rel(unsigned* p, unsigned v) {
    asm volatile("st.global.release.gpu.u32 [%0], %1;" :: "l"(p), "r"(v) : "memory");
}

// ================= Repack x: g_Ap[(mtile*32+kc)*4096 + r*32 + kperm] =================
__global__ __launch_bounds__(256) void repack_x(const float* __restrict__ x) {
    const int kc = blockIdx.x;      // 0..31
    const int mtile = blockIdx.y;   // 0..127
    const int tid = threadIdx.x;
    const int r = tid >> 1;
    const int kk0 = (tid & 1) * 16;

    const int R = mtile * 128 + r;
    const int tt = R >> 5, bb = R & 31;
    const float* src = x + ((size_t)bb * T_ + (size_t)(T_ - 1 - tt)) * D_ + kc * 32 + kk0;
    float* dst = g_Ap + ((size_t)(mtile * 32 + kc)) * 4096 + r * 32;

#pragma unroll
    for (int j = 0; j < 4; ++j) {
        float4 v = *(const float4*)(src + j * 4);
        int kk = kk0 + j * 4;
        dst[((kk + 0) >> 3) * 8 + kperm((kk + 0) & 7)] = __uint_as_float(f2tf32(v.x));
        dst[((kk + 1) >> 3) * 8 + kperm((kk + 1) & 7)] = __uint_as_float(f2tf32(v.y));
        dst[((kk + 2) >> 3) * 8 + kperm((kk + 2) & 7)] = __uint_as_float(f2tf32(v.z));
        dst[((kk + 3) >> 3) * 8 + kperm((kk + 3) & 7)] = __uint_as_float(f2tf32(v.w));
    }
}

// ================= Repack W (x-rows): g_Bp[(ntile*32+kc)*4096 + n*32 + kperm] =================
__global__ __launch_bounds__(256) void repack_w(const float* __restrict__ W) {
    const int kc = blockIdx.x;     // 0..31
    const int ntile = blockIdx.y;  // 0..31
    const int tid = threadIdx.x;
    const int kk = tid >> 3;
    const int nb = (tid & 7) * 16;

    const int kpos = (kk >> 3) * 8 + kperm(kk & 7);
    const float* src = W + (size_t)(kc * 32 + kk) * ZN + ntile * 128 + nb;
    float* dst = g_Bp + ((size_t)(ntile * 32 + kc)) * 4096;

#pragma unroll
    for (int j = 0; j < 4; ++j) {
        float4 v = *(const float4*)(src + j * 4);
        int n = nb + j * 4;
        dst[(n + 0) * 32 + kpos] = __uint_as_float(f2tf32(v.x));
        dst[(n + 1) * 32 + kpos] = __uint_as_float(f2tf32(v.y));
        dst[(n + 2) * 32 + kpos] = __uint_as_float(f2tf32(v.z));
        dst[(n + 3) * 32 + kpos] = __uint_as_float(f2tf32(v.w));
    }
}

// ======= Phase 1: G = x_rev @ Wx + bias (tf32 mma, 128x256 tile, 3-stage cp.async) ========
#define ST 40
#define P1T 512
__global__ __launch_bounds__(P1T, 1) void gemm_xw_tc(const float* __restrict__ bias) {
    extern __shared__ float smemf[];   // 3 stages x (A 128*ST + B 256*ST)

    const int tid = threadIdx.x;
    const int wid = tid >> 5, lane = tid & 31;
    const int bn = blockIdx.x, bm = blockIdx.y;
    const int wm = wid >> 3, wn = wid & 7;   // warp grid 2m x 8n
    const int l4 = lane & 3, g4 = lane >> 2;

    auto issue = [&](int c, int s) {
        float* dstA = smemf + s * (384 * ST);
        float* dstB = dstA + 128 * ST;
        const float* srcA = g_Ap + ((size_t)(bm * 32 + c)) * 4096;
#pragma unroll
        for (int j = 0; j < 2; ++j) {
            int G = tid + j * P1T;
            int r = G >> 3, g = G & 7;
            cpa16(dstA + r * ST + g * 4, srcA + r * 32 + g * 4);
        }
#pragma unroll
        for (int j = 0; j < 4; ++j) {
            int G = tid + j * P1T;
            int r = G >> 3, g = G & 7;
            const float* srcB = g_Bp + ((size_t)((2 * bn + (r >> 7)) * 32 + c)) * 4096;
            cpa16(dstB + r * ST + g * 4, srcB + (r & 127) * 32 + g * 4);
        }
        asm volatile("cp.async.commit_group;");
    };

    float acc[4][4][4];
#pragma unroll
    for (int i = 0; i < 4; ++i)
#pragma unroll
        for (int j = 0; j < 4; ++j)
#pragma unroll
            for (int e = 0; e < 4; ++e) acc[i][j][e] = 0.0f;

    issue(0, 0);
    issue(1, 1);
    issue(2, 2);

    int stage = 0;
    for (int c = 0; c < 32; ++c) {
        asm volatile("cp.async.wait_group 2;");
        __syncthreads();
        const float* A_s = smemf + stage * (384 * ST);
        const float* B_s = A_s + 128 * ST;

#pragma unroll
        for (int q = 0; q < 4; ++q) {
            uint32_t a[4][4], b[4][2];
#pragma unroll
            for (int mt = 0; mt < 4; ++mt) {
                int m = wm * 64 + mt * 16 + g4;
                uint2 lo = *(const uint2*)&A_s[m * ST + q * 8 + 2 * l4];
                uint2 hi = *(const uint2*)&A_s[(m + 8) * ST + q * 8 + 2 * l4];
                a[mt][0] = lo.x; a[mt][1] = hi.x; a[mt][2] = lo.y; a[mt][3] = hi.y;
            }
#pragma unroll
            for (int nt = 0; nt < 4; ++nt) {
                int n = wn * 32 + nt * 8 + g4;
                uint2 bv = *(const uint2*)&B_s[n * ST + q * 8 + 2 * l4];
                b[nt][0] = bv.x; b[nt][1] = bv.y;
            }
#pragma unroll
            for (int mt = 0; mt < 4; ++mt)
#pragma unroll
                for (int nt = 0; nt < 4; ++nt)
                    mma_m16n8k8(acc[mt][nt], a[mt], b[nt][0], b[nt][1]);
        }
        __syncthreads();
        if (c + 3 < 32) issue(c + 3, stage);
        stage = (stage == 2) ? 0 : stage + 1;
    }

#pragma unroll
    for (int mt = 0; mt < 4; ++mt) {
#pragma unroll
        for (int nt = 0; nt < 4; ++nt) {
            int R = bm * 128 + wm * 64 + mt * 16 + g4;
            int C = bn * 256 + wn * 32 + nt * 8 + 2 * l4;
            float2 bb2 = *(const float2*)(bias + C);
            float2 v0 = make_float2(acc[mt][nt][0] + bb2.x, acc[mt][nt][1] + bb2.y);
            float2 v1 = make_float2(acc[mt][nt][2] + bb2.x, acc[mt][nt][3] + bb2.y);
            *(float2*)&g_G[(size_t)R * ZN + C] = v0;
            *(float2*)&g_G[(size_t)(R + 8) * ZN + C] = v1;
        }
    }
}

// ================= Phase 2: persistent LSTM (tf32 mma, per-warp producer polling) =========
// 16 warps = 8 K-groups x 2 N-halves. red double-buffered; only warps 0-7 do
// reduce/gates; warps 8-15 skip ahead to absorb producer skew.
#define NT2 512
#define RED_S 40
__global__ __launch_bounds__(NT2, 1) void lstm_seq_tc(const float* __restrict__ Wfull,
                                                      float* __restrict__ out) {
    extern __shared__ uint32_t dynsmem[];
    uint32_t* W_s = dynsmem;                         // 16 slabs * 2048 words = 32768 words
    float* redb = (float*)(dynsmem + 16 * 2048);     // 2 * 8 * 32 * 40 floats

    const float* Wh = Wfull + (size_t)D_ * ZN;
    const int tid = threadIdx.x;
    const int wid = tid >> 5, lane = tid & 31;
    const int l4 = lane & 3, g4 = lane >> 2;
    const int bid = blockIdx.x;
    const int n0 = bid * 8;
    const int pb = (tid >> 3) & 31;
    const int pn = tid & 7;
    const bool lower = wid < 8;
    const int kgrp = wid >> 1, nh = wid & 1;
    const int hw = bid * 256 + ((pb >> 4) & 1) * 128 + (pb & 7) * 16 +
                   (pn & 3) * 4 + ((pn >> 2) & 1) * 2 + ((pb >> 3) & 1);

    // ---- load weight slice into SMEM, warp-centric pack ----
    for (int idx = tid; idx < 1024 * 32; idx += NT2) {
        int k = idx >> 5, c = idx & 31;
        float w = __ldg(Wh + (size_t)k * ZN + (c >> 3) * H_ + n0 + (c & 7));
        int kg = k >> 7, q = (k >> 3) & 15, l4k = k & 3, jk = (k >> 2) & 1;
        int nhh = (c >> 4) & 1, nt = (c >> 3) & 1, g4c = c & 7;
        W_s[(kg * 2 + nhh) * 2048 + q * 128 + (g4c * 4 + l4k) * 4 + nt * 2 + jk] = f2tf32(w);
    }
    __syncthreads();

    float c_reg = 0.0f;
    float gq[4];
    if (lower) {
#pragma unroll
        for (int g = 0; g < 4; ++g)
            gq[g] = g_G[(size_t)(32 + pb) * ZN + g * H_ + n0 + pn];
    }

    // ---- step 0: h = 0, z = G[0] ----
    if (lower) {
        float iv = g_G[(size_t)pb * ZN + 0 * H_ + n0 + pn];
        float jv = g_G[(size_t)pb * ZN + 1 * H_ + n0 + pn];
        float ov = g_G[(size_t)pb * ZN + 3 * H_ + n0 + pn];
        c_reg = sigf(iv) * tanhf(jv);
        float hv = sigf(ov) * tanhf(c_reg);
        __stcg(&g_h[1][hw], __uint_as_float(f2tf32(hv)));
    }
    __syncthreads();
    if (tid == 0) st_rel(&g_flags[bid * 32], 1u);
    if (lower) __stcs(&out[(size_t)pb * (T_ * H_) + n0 + pn], c_reg);

    const uint4* Wq = (const uint4*)W_s + (size_t)wid * 512;

    for (int t = 1; t < T_; ++t) {
        // ---- prefetch G[t+1] (flag-independent; consumed next iteration) ----
        float gn[4];
        if (lower) {
            int tn = (t + 1 < T_) ? t + 1 : T_ - 1;
#pragma unroll
            for (int g = 0; g < 4; ++g)
                gn[g] = g_G[((size_t)tn * B_ + pb) * ZN + g * H_ + n0 + pn];
        }

        // ---- per-warp poll: only this warp's 16 producer blocks ----
        if (lane < 16) {
            const unsigned* fp = &g_flags[(kgrp * 16 + lane) * 32];
            while (ld_acq(fp) < (unsigned)t) { }
        }
        __syncwarp();

        const float4* hb = (const float4*)g_h[t & 1];
        float acc[2][2][4];
#pragma unroll
        for (int mt = 0; mt < 2; ++mt)
#pragma unroll
            for (int nt = 0; nt < 2; ++nt)
#pragma unroll
                for (int e = 0; e < 4; ++e) acc[mt][nt][e] = 0.0f;

#pragma unroll
        for (int q = 0; q < 16; ++q) {
            int k8 = kgrp * 16 + q;
            uint4 bv = Wq[q * 32 + lane];
            uint32_t a[2][4];
#pragma unroll
            for (int mt = 0; mt < 2; ++mt) {
                float4 v = __ldcg(&hb[k8 * 64 + mt * 32 + g4 * 4 + l4]);
                a[mt][0] = __float_as_uint(v.x); a[mt][1] = __float_as_uint(v.y);
                a[mt][2] = __float_as_uint(v.z); a[mt][3] = __float_as_uint(v.w);
            }
#pragma unroll
            for (int mt = 0; mt < 2; ++mt) {
                mma_m16n8k8(acc[mt][0], a[mt], bv.x, bv.y);
                mma_m16n8k8(acc[mt][1], a[mt], bv.z, bv.w);
            }
        }

        // ---- store partials into parity buffer ----
        float* red = redb + (t & 1) * (8 * 32 * RED_S);
#pragma unroll
        for (int mt = 0; mt < 2; ++mt) {
#pragma unroll
            for (int nt = 0; nt < 2; ++nt) {
                int row = mt * 16 + g4;
                int col = nh * 16 + nt * 8 + 2 * l4;
                *(float2*)&red[kgrp * (32 * RED_S) + row * RED_S + col] =
                    make_float2(acc[mt][nt][0], acc[mt][nt][1]);
                *(float2*)&red[kgrp * (32 * RED_S) + (row + 8) * RED_S + col] =
                    make_float2(acc[mt][nt][2], acc[mt][nt][3]);
            }
        }
        __syncthreads();   // all 16 warps: partials visible. Upper warps then run ahead.

        if (lower) {
            float z[4];
#pragma unroll
            for (int g = 0; g < 4; ++g) {
                float s = gq[g];
#pragma unroll
                for (int kg = 0; kg < 8; ++kg)
                    s += red[kg * (32 * RED_S) + pb * RED_S + g * 8 + pn];
                z[g] = s;
            }
            c_reg = sigf(z[2] + 1.0f) * c_reg + sigf(z[0]) * tanhf(z[1]);
            float hv = sigf(z[3]) * tanhf(c_reg);
            __stcg(&g_h[(t + 1) & 1][hw], __uint_as_float(f2tf32(hv)));
            asm volatile("bar.sync 2, 256;" ::: "memory");   // lower warps only
            if (tid == 0) st_rel(&g_flags[bid * 32], (unsigned)(t + 1));
            __stcs(&out[(size_t)pb * (T_ * H_) + (size_t)t * H_ + n0 + pn], c_reg);
#pragma unroll
            for (int g = 0; g < 4; ++g) gq[g] = gn[g];
        }
    }

    // ---- reset flags for deterministic graph replay ----
    __syncthreads();
    if (tid == 0) atomicAdd(&g_done, 1u);
    if (bid == 0) {
        if (tid == 0) {
            while (*(volatile unsigned*)&g_done < (unsigned)NBLK) { }
        }
        __syncthreads();
        if (tid < NBLK) g_flags[tid * 32] = 0u;
        __syncthreads();
        if (tid == 0) { __threadfence(); g_done = 0u; }
    }
}

// ---------------- launch ----------------
extern "C" void kernel_launch(void* const* d_in, const int* in_sizes, int n_in,
                              void* d_out, int out_size) {
    (void)in_sizes; (void)n_in; (void)out_size;
    const float* x    = (const float*)d_in[0];
    const float* kern = (const float*)d_in[2];
    const float* bias = (const float*)d_in[3];
    float* out = (float*)d_out;

    const int smem1 = 3 * 384 * ST * 4;                         // 184320 B
    const int smem2 = (16 * 2048 + 2 * 8 * 32 * RED_S) * 4;     // 212992 B
    cudaFuncSetAttribute(gemm_xw_tc, cudaFuncAttributeMaxDynamicSharedMemorySize, smem1);
    cudaFuncSetAttribute(lstm_seq_tc, cudaFuncAttributeMaxDynamicSharedMemorySize, smem2);

    repack_x<<<dim3(32, 128), 256>>>(x);
    repack_w<<<dim3(32, 32), 256>>>(kern);
    gemm_xw_tc<<<dim3(16, 128), P1T, smem1>>>(bias);
    lstm_seq_tc<<<NBLK, NT2, smem2>>>(kern, out);
}

// round 10
// speedup vs baseline: 1.2975x; 1.2975x over previous
#include <cuda_runtime.h>
#include <cuda_bf16.h>
#include <cuda_fp16.h>
#include <math.h>
#include <stdint.h>

#define B_ 32
#define T_ 512
#define D_ 1024
#define H_ 1024
#define ZN 4096
#define NBLK 128

// ---------------- device scratch ----------------
__device__ float g_G[(size_t)T_ * B_ * ZN];        // 256MB: x@Wx + bias, row r = t*32+b (reversed time)
__device__ unsigned g_Ap[(size_t)128 * 32 * 2048]; // 32MB: repacked x (fp16 half2, kperm, tiled 128x32)
__device__ unsigned g_Bp[(size_t)32 * 32 * 2048];  // 8MB:  repacked Wx (fp16 half2, kperm, tiled 128x32)
__device__ float g_h[2][H_ * B_];                  // double-buffered h, mma-fragment-packed
__device__ unsigned g_flags[NBLK * 32];            // per-block progress flags, 128B apart
__device__ unsigned g_done = 0;

// ---------------- helpers ----------------
__device__ __forceinline__ float sigf(float x) { return 1.0f / (1.0f + __expf(-x)); }

__device__ __forceinline__ uint32_t f2tf32(float x) {
    uint32_t u;
    asm("cvt.rna.tf32.f32 %0, %1;" : "=r"(u) : "f"(x));
    return u;
}

__device__ __forceinline__ uint32_t packh2(float a, float b) {
    __half2 h = __halves2half2(__float2half_rn(a), __float2half_rn(b));
    return *(uint32_t*)&h;
}

// fp16 mma m16n8k16, fp32 accumulate
__device__ __forceinline__ void mma_f16(float* c, const uint32_t* a, uint32_t b0, uint32_t b1) {
    asm volatile(
        "mma.sync.aligned.m16n8k16.row.col.f32.f16.f16.f32 "
        "{%0,%1,%2,%3}, {%4,%5,%6,%7}, {%8,%9}, {%0,%1,%2,%3};"
        : "+f"(c[0]), "+f"(c[1]), "+f"(c[2]), "+f"(c[3])
        : "r"(a[0]), "r"(a[1]), "r"(a[2]), "r"(a[3]), "r"(b0), "r"(b1));
}

// tf32 mma m16n8k8 (phase 2)
__device__ __forceinline__ void mma_m16n8k8(float* c, const uint32_t* a, uint32_t b0, uint32_t b1) {
    asm volatile(
        "mma.sync.aligned.m16n8k8.row.col.f32.tf32.tf32.f32 "
        "{%0,%1,%2,%3}, {%4,%5,%6,%7}, {%8,%9}, {%0,%1,%2,%3};"
        : "+f"(c[0]), "+f"(c[1]), "+f"(c[2]), "+f"(c[3])
        : "r"(a[0]), "r"(a[1]), "r"(a[2]), "r"(a[3]), "r"(b0), "r"(b1));
}

// k-permute within an 8-word group so frag pairs (w, w+4) are adjacent (LDS.64)
__device__ __forceinline__ int kperm(int r) { return ((r & 3) << 1) | (r >> 2); }

__device__ __forceinline__ void cpa16(void* dst, const void* src) {
    unsigned s = (unsigned)__cvta_generic_to_shared(dst);
    asm volatile("cp.async.cg.shared.global [%0], [%1], 16;" :: "r"(s), "l"(src));
}

__device__ __forceinline__ unsigned ld_acq(const unsigned* p) {
    unsigned v;
    asm volatile("ld.global.acquire.gpu.u32 %0, [%1];" : "=r"(v) : "l"(p) : "memory");
    return v;
}
__device__ __forceinline__ void st_rel(unsigned* p, unsigned v) {
    asm volatile("st.global.release.gpu.u32 [%0], %1;" :: "l"(p), "r"(v) : "memory");
}

// ========== Repack x (fp16): g_Ap[(mtile*32+kc)*2048 + r*16 + word] ==========
// word w=k/2 holds halves (k, k+1); position = (w>>3)*8 + kperm(w&7)
__global__ __launch_bounds__(256) void repack_x(const float* __restrict__ x) {
    const int kc = blockIdx.x;      // 0..31
    const int mtile = blockIdx.y;   // 0..127
    const int tid = threadIdx.x;
    const int r = tid >> 1;         // row 0..127
    const int s = tid & 1;          // k-half (16 k each)

    const int R = mtile * 128 + r;
    const int tt = R >> 5, bb = R & 31;
    const float* src = x + ((size_t)bb * T_ + (size_t)(T_ - 1 - tt)) * D_ + kc * 32 + s * 16;
    unsigned* dst = g_Ap + ((size_t)(mtile * 32 + kc)) * 2048 + r * 16 + s * 8;

#pragma unroll
    for (int j = 0; j < 4; ++j) {
        float4 v = *(const float4*)(src + j * 4);
        dst[kperm(2 * j + 0)] = packh2(v.x, v.y);
        dst[kperm(2 * j + 1)] = packh2(v.z, v.w);
    }
}

// ========== Repack W x-rows (fp16): g_Bp[(ntile*32+kc)*2048 + n*16 + word] ==========
__global__ __launch_bounds__(256) void repack_w(const float* __restrict__ W) {
    const int kc = blockIdx.x;     // 0..31
    const int ntile = blockIdx.y;  // 0..31
    const int tid = threadIdx.x;
    const int p  = tid >> 4;       // k-pair 0..15 (k = 2p, 2p+1)
    const int ng = tid & 15;       // n-group of 8
    const int n  = ng * 8;

    const int wpos = (p >> 3) * 8 + kperm(p & 7);
    const float* r0 = W + (size_t)(kc * 32 + 2 * p) * ZN + ntile * 128 + n;
    const float* r1 = r0 + ZN;
    unsigned* dst = g_Bp + ((size_t)(ntile * 32 + kc)) * 2048;

#pragma unroll
    for (int j = 0; j < 8; ++j)
        dst[(n + j) * 16 + wpos] = packh2(r0[j], r1[j]);
}

// ======= Phase 1: G = x_rev @ Wx + bias (fp16 mma m16n8k16, 3-stage cp.async) ========
#define ST1 24   // smem row stride (words): conflict-free LDS.64 phases
#define P1T 256
__global__ __launch_bounds__(P1T, 2) void gemm_xw_tc(const float* __restrict__ bias) {
    extern __shared__ unsigned smemu[];   // 3 stages x (A 128*ST1 + B 128*ST1)

    const int tid = threadIdx.x;
    const int wid = tid >> 5, lane = tid & 31;
    const int bn = blockIdx.x, bm = blockIdx.y;
    const int wm = wid >> 2, wn = wid & 3;   // 2m x 4n warps, warp tile 64x32
    const int l4 = lane & 3, g4 = lane >> 2;

    auto issue = [&](int c, int s) {
        unsigned* dstA = smemu + s * (256 * ST1);
        unsigned* dstB = dstA + 128 * ST1;
        const unsigned* srcA = g_Ap + ((size_t)(bm * 32 + c)) * 2048;
        const unsigned* srcB = g_Bp + ((size_t)(bn * 32 + c)) * 2048;
#pragma unroll
        for (int j = 0; j < 2; ++j) {
            int G = tid + j * P1T;          // 0..511
            int r = G >> 2, g = G & 3;      // 4 words per cp
            cpa16(dstA + r * ST1 + g * 4, srcA + r * 16 + g * 4);
            cpa16(dstB + r * ST1 + g * 4, srcB + r * 16 + g * 4);
        }
        asm volatile("cp.async.commit_group;");
    };

    float acc[4][4][4];
#pragma unroll
    for (int i = 0; i < 4; ++i)
#pragma unroll
        for (int j = 0; j < 4; ++j)
#pragma unroll
            for (int e = 0; e < 4; ++e) acc[i][j][e] = 0.0f;

    issue(0, 0);
    issue(1, 1);
    issue(2, 2);

    int stage = 0;
    for (int c = 0; c < 32; ++c) {
        asm volatile("cp.async.wait_group 2;");
        __syncthreads();
        const unsigned* A_s = smemu + stage * (256 * ST1);
        const unsigned* B_s = A_s + 128 * ST1;

#pragma unroll
        for (int q = 0; q < 2; ++q) {       // two k16 steps per 32-k chunk
            uint32_t a[4][4], b[4][2];
#pragma unroll
            for (int mt = 0; mt < 4; ++mt) {
                int m = wm * 64 + mt * 16 + g4;
                uint2 lo = *(const uint2*)&A_s[m * ST1 + q * 8 + 2 * l4];
                uint2 hi = *(const uint2*)&A_s[(m + 8) * ST1 + q * 8 + 2 * l4];
                a[mt][0] = lo.x; a[mt][1] = hi.x; a[mt][2] = lo.y; a[mt][3] = hi.y;
            }
#pragma unroll
            for (int nt = 0; nt < 4; ++nt) {
                int n = wn * 32 + nt * 8 + g4;
                uint2 bv = *(const uint2*)&B_s[n * ST1 + q * 8 + 2 * l4];
                b[nt][0] = bv.x; b[nt][1] = bv.y;
            }
#pragma unroll
            for (int mt = 0; mt < 4; ++mt)
#pragma unroll
                for (int nt = 0; nt < 4; ++nt)
                    mma_f16(acc[mt][nt], a[mt], b[nt][0], b[nt][1]);
        }
        __syncthreads();
        if (c + 3 < 32) issue(c + 3, stage);
        stage = (stage == 2) ? 0 : stage + 1;
    }

#pragma unroll
    for (int mt = 0; mt < 4; ++mt) {
#pragma unroll
        for (int nt = 0; nt < 4; ++nt) {
            int R = bm * 128 + wm * 64 + mt * 16 + g4;
            int C = bn * 128 + wn * 32 + nt * 8 + 2 * l4;
            float2 bb2 = *(const float2*)(bias + C);
            float2 v0 = make_float2(acc[mt][nt][0] + bb2.x, acc[mt][nt][1] + bb2.y);
            float2 v1 = make_float2(acc[mt][nt][2] + bb2.x, acc[mt][nt][3] + bb2.y);
            *(float2*)&g_G[(size_t)R * ZN + C] = v0;
            *(float2*)&g_G[(size_t)(R + 8) * ZN + C] = v1;
        }
    }
}

// ================= Phase 2: persistent LSTM (tf32 mma, per-warp producer polling) =========
// EXACT R7 version (best known: 1.94 ms).
#define NT2 512
#define RED_S 40
__global__ __launch_bounds__(NT2, 1) void lstm_seq_tc(const float* __restrict__ Wfull,
                                                      float* __restrict__ out) {
    extern __shared__ uint32_t dynsmem[];
    uint32_t* W_s = dynsmem;                         // 16 slabs * 2048 words
    float* red = (float*)(dynsmem + 16 * 2048);      // 8 * 32 * 40 floats

    const float* Wh = Wfull + (size_t)D_ * ZN;
    const int tid = threadIdx.x;
    const int wid = tid >> 5, lane = tid & 31;
    const int l4 = lane & 3, g4 = lane >> 2;
    const int bid = blockIdx.x;
    const int n0 = bid * 8;
    const int pb = (tid >> 3) & 31;
    const int pn = tid & 7;
    const bool active = tid < 256;
    const int kgrp = wid >> 1, nh = wid & 1;
    const int hw = bid * 256 + ((pb >> 4) & 1) * 128 + (pb & 7) * 16 +
                   (pn & 3) * 4 + ((pn >> 2) & 1) * 2 + ((pb >> 3) & 1);

    // ---- load weight slice into SMEM, warp-centric pack ----
    for (int idx = tid; idx < 1024 * 32; idx += NT2) {
        int k = idx >> 5, c = idx & 31;
        float w = __ldg(Wh + (size_t)k * ZN + (c >> 3) * H_ + n0 + (c & 7));
        int kg = k >> 7, q = (k >> 3) & 15, l4k = k & 3, jk = (k >> 2) & 1;
        int nhh = (c >> 4) & 1, nt = (c >> 3) & 1, g4c = c & 7;
        W_s[(kg * 2 + nhh) * 2048 + q * 128 + (g4c * 4 + l4k) * 4 + nt * 2 + jk] = f2tf32(w);
    }
    __syncthreads();

    float c_reg = 0.0f;
    float gq[4];
    if (active) {
#pragma unroll
        for (int g = 0; g < 4; ++g)
            gq[g] = g_G[(size_t)(32 + pb) * ZN + g * H_ + n0 + pn];
    }

    // ---- step 0: h = 0, z = G[0] ----
    if (active) {
        float iv = g_G[(size_t)pb * ZN + 0 * H_ + n0 + pn];
        float jv = g_G[(size_t)pb * ZN + 1 * H_ + n0 + pn];
        float ov = g_G[(size_t)pb * ZN + 3 * H_ + n0 + pn];
        c_reg = sigf(iv) * tanhf(jv);
        float hv = sigf(ov) * tanhf(c_reg);
        __stcg(&g_h[1][hw], __uint_as_float(f2tf32(hv)));
    }
    __syncthreads();
    if (tid == 0) st_rel(&g_flags[bid * 32], 1u);
    if (active) __stcs(&out[(size_t)pb * (T_ * H_) + n0 + pn], c_reg);

    const uint4* Wq = (const uint4*)W_s + (size_t)wid * 512;

    for (int t = 1; t < T_; ++t) {
        // ---- prefetch G[t+1] (flag-independent; consumed next iteration) ----
        float gn[4];
        if (active) {
            int tn = (t + 1 < T_) ? t + 1 : T_ - 1;
#pragma unroll
            for (int g = 0; g < 4; ++g)
                gn[g] = g_G[((size_t)tn * B_ + pb) * ZN + g * H_ + n0 + pn];
        }

        // ---- per-warp poll: only this warp's 16 producer blocks ----
        if (lane < 16) {
            const unsigned* fp = &g_flags[(kgrp * 16 + lane) * 32];
            while (ld_acq(fp) < (unsigned)t) { }
        }
        __syncwarp();

        const float4* hb = (const float4*)g_h[t & 1];
        float acc[2][2][4];
#pragma unroll
        for (int mt = 0; mt < 2; ++mt)
#pragma unroll
            for (int nt = 0; nt < 2; ++nt)
#pragma unroll
                for (int e = 0; e < 4; ++e) acc[mt][nt][e] = 0.0f;

#pragma unroll
        for (int q = 0; q < 16; ++q) {
            int k8 = kgrp * 16 + q;
            uint4 bv = Wq[q * 32 + lane];   // LDS.128: both n-tile fragments
            uint32_t a[2][4];
#pragma unroll
            for (int mt = 0; mt < 2; ++mt) {
                float4 v = __ldcg(&hb[k8 * 64 + mt * 32 + g4 * 4 + l4]);
                a[mt][0] = __float_as_uint(v.x); a[mt][1] = __float_as_uint(v.y);
                a[mt][2] = __float_as_uint(v.z); a[mt][3] = __float_as_uint(v.w);
            }
#pragma unroll
            for (int mt = 0; mt < 2; ++mt) {
                mma_m16n8k8(acc[mt][0], a[mt], bv.x, bv.y);
                mma_m16n8k8(acc[mt][1], a[mt], bv.z, bv.w);
            }
        }

        // ---- store per-kgrp partials ----
#pragma unroll
        for (int mt = 0; mt < 2; ++mt) {
#pragma unroll
            for (int nt = 0; nt < 2; ++nt) {
                int row = mt * 16 + g4;
                int col = nh * 16 + nt * 8 + 2 * l4;
                *(float2*)&red[kgrp * (32 * RED_S) + row * RED_S + col] =
                    make_float2(acc[mt][nt][0], acc[mt][nt][1]);
                *(float2*)&red[kgrp * (32 * RED_S) + (row + 8) * RED_S + col] =
                    make_float2(acc[mt][nt][2], acc[mt][nt][3]);
            }
        }
        __syncthreads();

        // ---- merged reduce (8 partials) + gates + h store ----
        if (active) {
            float z[4];
#pragma unroll
            for (int g = 0; g < 4; ++g) {
                float s = gq[g];
#pragma unroll
                for (int kg = 0; kg < 8; ++kg)
                    s += red[kg * (32 * RED_S) + pb * RED_S + g * 8 + pn];
                z[g] = s;
            }
            c_reg = sigf(z[2] + 1.0f) * c_reg + sigf(z[0]) * tanhf(z[1]);
            float hv = sigf(z[3]) * tanhf(c_reg);
            __stcg(&g_h[(t + 1) & 1][hw], __uint_as_float(f2tf32(hv)));
        }
        __syncthreads();
        if (tid == 0) st_rel(&g_flags[bid * 32], (unsigned)(t + 1));
        if (active) __stcs(&out[(size_t)pb * (T_ * H_) + (size_t)t * H_ + n0 + pn], c_reg);

#pragma unroll
        for (int g = 0; g < 4; ++g) gq[g] = gn[g];
    }

    // ---- reset flags for deterministic graph replay ----
    __syncthreads();
    if (tid == 0) atomicAdd(&g_done, 1u);
    if (bid == 0) {
        if (tid == 0) {
            while (*(volatile unsigned*)&g_done < (unsigned)NBLK) { }
        }
        __syncthreads();
        if (tid < NBLK) g_flags[tid * 32] = 0u;
        __syncthreads();
        if (tid == 0) { __threadfence(); g_done = 0u; }
    }
}

// ---------------- launch ----------------
extern "C" void kernel_launch(void* const* d_in, const int* in_sizes, int n_in,
                              void* d_out, int out_size) {
    (void)in_sizes; (void)n_in; (void)out_size;
    const float* x    = (const float*)d_in[0];
    const float* kern = (const float*)d_in[2];
    const float* bias = (const float*)d_in[3];
    float* out = (float*)d_out;

    const int smem1 = 3 * 256 * ST1 * 4;                    // 73728 B (2 blocks/SM)
    const int smem2 = (16 * 2048 + 8 * 32 * RED_S) * 4;     // 172032 B
    cudaFuncSetAttribute(gemm_xw_tc, cudaFuncAttributeMaxDynamicSharedMemorySize, smem1);
    cudaFuncSetAttribute(lstm_seq_tc, cudaFuncAttributeMaxDynamicSharedMemorySize, smem2);

    repack_x<<<dim3(32, 128), 256>>>(x);
    repack_w<<<dim3(32, 32), 256>>>(kern);
    gemm_xw_tc<<<dim3(32, 128), P1T, smem1>>>(bias);
    lstm_seq_tc<<<NBLK, NT2, smem2>>>(kern, out);
}

// round 11
// speedup vs baseline: 1.6447x; 1.2676x over previous
#include <cuda_runtime.h>
#include <cuda_bf16.h>
#include <cuda_fp16.h>
#include <math.h>
#include <stdint.h>

#define B_ 32
#define T_ 512
#define D_ 1024
#define H_ 1024
#define ZN 4096
#define NBLK 128

// ---------------- device scratch ----------------
__device__ float g_G[(size_t)T_ * B_ * ZN];        // 256MB: x@Wx + bias, row r = t*32+b (reversed time)
__device__ unsigned g_Ap[(size_t)128 * 32 * 2048]; // 32MB: repacked x (fp16 half2, kperm, tiled 128x32)
__device__ unsigned g_Bp[(size_t)32 * 32 * 2048];  // 8MB:  repacked Wx (fp16 half2, kperm, tiled 128x32)
__device__ unsigned g_h16[2][16384];               // 128KB: double-buffered h, fp16, mma-frag packed
__device__ unsigned g_flags[NBLK * 32];            // per-block progress flags, 128B apart
__device__ unsigned g_done = 0;

// ---------------- helpers ----------------
__device__ __forceinline__ float sigf(float x) { return 1.0f / (1.0f + __expf(-x)); }

__device__ __forceinline__ uint32_t packh2(float a, float b) {
    __half2 h = __halves2half2(__float2half_rn(a), __float2half_rn(b));
    return *(uint32_t*)&h;
}

// fp16 mma m16n8k16, fp32 accumulate
__device__ __forceinline__ void mma_f16(float* c, const uint32_t* a, uint32_t b0, uint32_t b1) {
    asm volatile(
        "mma.sync.aligned.m16n8k16.row.col.f32.f16.f16.f32 "
        "{%0,%1,%2,%3}, {%4,%5,%6,%7}, {%8,%9}, {%0,%1,%2,%3};"
        : "+f"(c[0]), "+f"(c[1]), "+f"(c[2]), "+f"(c[3])
        : "r"(a[0]), "r"(a[1]), "r"(a[2]), "r"(a[3]), "r"(b0), "r"(b1));
}

// k-permute within an 8-word group so frag pairs (w, w+4) are adjacent (LDS.64)
__device__ __forceinline__ int kperm(int r) { return ((r & 3) << 1) | (r >> 2); }

__device__ __forceinline__ void cpa16(void* dst, const void* src) {
    unsigned s = (unsigned)__cvta_generic_to_shared(dst);
    asm volatile("cp.async.cg.shared.global [%0], [%1], 16;" :: "r"(s), "l"(src));
}

__device__ __forceinline__ unsigned ld_acq(const unsigned* p) {
    unsigned v;
    asm volatile("ld.global.acquire.gpu.u32 %0, [%1];" : "=r"(v) : "l"(p) : "memory");
    return v;
}
__device__ __forceinline__ void st_rel(unsigned* p, unsigned v) {
    asm volatile("st.global.release.gpu.u32 [%0], %1;" :: "l"(p), "r"(v) : "memory");
}

// ========== Repack x (fp16): g_Ap[(mtile*32+kc)*2048 + r*16 + word] ==========
__global__ __launch_bounds__(256) void repack_x(const float* __restrict__ x) {
    const int kc = blockIdx.x;      // 0..31
    const int mtile = blockIdx.y;   // 0..127
    const int tid = threadIdx.x;
    const int r = tid >> 1;
    const int s = tid & 1;

    const int R = mtile * 128 + r;
    const int tt = R >> 5, bb = R & 31;
    const float* src = x + ((size_t)bb * T_ + (size_t)(T_ - 1 - tt)) * D_ + kc * 32 + s * 16;
    unsigned* dst = g_Ap + ((size_t)(mtile * 32 + kc)) * 2048 + r * 16 + s * 8;

#pragma unroll
    for (int j = 0; j < 4; ++j) {
        float4 v = *(const float4*)(src + j * 4);
        dst[kperm(2 * j + 0)] = packh2(v.x, v.y);
        dst[kperm(2 * j + 1)] = packh2(v.z, v.w);
    }
}

// ========== Repack W x-rows (fp16): g_Bp[(ntile*32+kc)*2048 + n*16 + word] ==========
__global__ __launch_bounds__(256) void repack_w(const float* __restrict__ W) {
    const int kc = blockIdx.x;     // 0..31
    const int ntile = blockIdx.y;  // 0..31
    const int tid = threadIdx.x;
    const int p  = tid >> 4;
    const int n  = (tid & 15) * 8;

    const int wpos = (p >> 3) * 8 + kperm(p & 7);
    const float* r0 = W + (size_t)(kc * 32 + 2 * p) * ZN + ntile * 128 + n;
    const float* r1 = r0 + ZN;
    unsigned* dst = g_Bp + ((size_t)(ntile * 32 + kc)) * 2048;

#pragma unroll
    for (int j = 0; j < 8; ++j)
        dst[(n + j) * 16 + wpos] = packh2(r0[j], r1[j]);
}

// ======= Phase 1: G = x_rev @ Wx + bias (fp16 mma m16n8k16, 3-stage cp.async) ========
#define ST1 24
#define P1T 256
__global__ __launch_bounds__(P1T, 2) void gemm_xw_tc(const float* __restrict__ bias) {
    extern __shared__ unsigned smemu[];

    const int tid = threadIdx.x;
    const int wid = tid >> 5, lane = tid & 31;
    const int bn = blockIdx.x, bm = blockIdx.y;
    const int wm = wid >> 2, wn = wid & 3;
    const int l4 = lane & 3, g4 = lane >> 2;

    auto issue = [&](int c, int s) {
        unsigned* dstA = smemu + s * (256 * ST1);
        unsigned* dstB = dstA + 128 * ST1;
        const unsigned* srcA = g_Ap + ((size_t)(bm * 32 + c)) * 2048;
        const unsigned* srcB = g_Bp + ((size_t)(bn * 32 + c)) * 2048;
#pragma unroll
        for (int j = 0; j < 2; ++j) {
            int G = tid + j * P1T;
            int r = G >> 2, g = G & 3;
            cpa16(dstA + r * ST1 + g * 4, srcA + r * 16 + g * 4);
            cpa16(dstB + r * ST1 + g * 4, srcB + r * 16 + g * 4);
        }
        asm volatile("cp.async.commit_group;");
    };

    float acc[4][4][4];
#pragma unroll
    for (int i = 0; i < 4; ++i)
#pragma unroll
        for (int j = 0; j < 4; ++j)
#pragma unroll
            for (int e = 0; e < 4; ++e) acc[i][j][e] = 0.0f;

    issue(0, 0);
    issue(1, 1);
    issue(2, 2);

    int stage = 0;
    for (int c = 0; c < 32; ++c) {
        asm volatile("cp.async.wait_group 2;");
        __syncthreads();
        const unsigned* A_s = smemu + stage * (256 * ST1);
        const unsigned* B_s = A_s + 128 * ST1;

#pragma unroll
        for (int q = 0; q < 2; ++q) {
            uint32_t a[4][4], b[4][2];
#pragma unroll
            for (int mt = 0; mt < 4; ++mt) {
                int m = wm * 64 + mt * 16 + g4;
                uint2 lo = *(const uint2*)&A_s[m * ST1 + q * 8 + 2 * l4];
                uint2 hi = *(const uint2*)&A_s[(m + 8) * ST1 + q * 8 + 2 * l4];
                a[mt][0] = lo.x; a[mt][1] = hi.x; a[mt][2] = lo.y; a[mt][3] = hi.y;
            }
#pragma unroll
            for (int nt = 0; nt < 4; ++nt) {
                int n = wn * 32 + nt * 8 + g4;
                uint2 bv = *(const uint2*)&B_s[n * ST1 + q * 8 + 2 * l4];
                b[nt][0] = bv.x; b[nt][1] = bv.y;
            }
#pragma unroll
            for (int mt = 0; mt < 4; ++mt)
#pragma unroll
                for (int nt = 0; nt < 4; ++nt)
                    mma_f16(acc[mt][nt], a[mt], b[nt][0], b[nt][1]);
        }
        __syncthreads();
        if (c + 3 < 32) issue(c + 3, stage);
        stage = (stage == 2) ? 0 : stage + 1;
    }

#pragma unroll
    for (int mt = 0; mt < 4; ++mt) {
#pragma unroll
        for (int nt = 0; nt < 4; ++nt) {
            int R = bm * 128 + wm * 64 + mt * 16 + g4;
            int C = bn * 128 + wn * 32 + nt * 8 + 2 * l4;
            float2 bb2 = *(const float2*)(bias + C);
            float2 v0 = make_float2(acc[mt][nt][0] + bb2.x, acc[mt][nt][1] + bb2.y);
            float2 v1 = make_float2(acc[mt][nt][2] + bb2.x, acc[mt][nt][3] + bb2.y);
            *(float2*)&g_G[(size_t)R * ZN + C] = v0;
            *(float2*)&g_G[(size_t)(R + 8) * ZN + C] = v1;
        }
    }
}

// ============ Phase 2: persistent LSTM (fp16 mma, K-split 16, per-warp polling) ===========
// 16 warps, warp w owns k in [w*64, w*64+64), all 32 z-cols. h fp16, fragment-packed:
// word(b,k2) = (c16*2 + mt)*128 + (g4b*4 + l4)*4 + hi*2 + rhi  (half2 words)
#define NT2 512
#define RED_S 40
__global__ __launch_bounds__(NT2, 1) void lstm_seq_tc(const float* __restrict__ Wfull,
                                                      float* __restrict__ out) {
    extern __shared__ uint32_t dynsmem[];
    uint32_t* W_s = dynsmem;                         // 16 slabs * 1024 words = 16384 (64KB)
    float* red = (float*)(dynsmem + 16384);          // 16 * 32 * 40 floats (80KB)

    const float* Wh = Wfull + (size_t)D_ * ZN;
    const int tid = threadIdx.x;
    const int wid = tid >> 5, lane = tid & 31;
    const int l4 = lane & 3, g4 = lane >> 2;
    const int bid = blockIdx.x;
    const int n0 = bid * 8;
    const int pb = (tid >> 3) & 31;
    const int pn = tid & 7;
    const bool active = tid < 256;

    // pointwise h-store address (half units): element (b=pb, k=n0+pn)
    const int hk = n0 + pn;
    const int hc16 = hk >> 4;
    const int hk2r = (hk >> 1) & 7;
    const int hword = (hc16 * 2 + (pb >> 4)) * 128 + ((pb & 7) * 4 + (hk2r & 3)) * 4 +
                      (hk2r >> 2) * 2 + ((pb >> 3) & 1);
    const int hbyte = hword * 4 + (hk & 1) * 2;

    // ---- pack weight slice into SMEM (fp16, warp-centric) ----
    // word = w*1024 + kk*256 + q128*128 + lane*4 + ntl*2 + hi
    for (int widx = tid; widx < 16384; widx += NT2) {
        int w = widx >> 10, rem = widx & 1023;
        int kk = rem >> 8, q128 = (rem >> 7) & 1;
        int lw = (rem >> 2) & 31, low2 = rem & 3;
        int nt = q128 * 2 + (low2 >> 1), hi = low2 & 1;
        int g4c = lw >> 2, l4w = lw & 3;
        int k = w * 64 + kk * 16 + (hi * 4 + l4w) * 2;
        int col = nt * H_ + n0 + g4c;
        W_s[widx] = packh2(__ldg(Wh + (size_t)k * ZN + col),
                           __ldg(Wh + (size_t)(k + 1) * ZN + col));
    }
    __syncthreads();

    float c_reg = 0.0f;
    float gq[4];
    if (active) {
#pragma unroll
        for (int g = 0; g < 4; ++g)
            gq[g] = g_G[(size_t)(32 + pb) * ZN + g * H_ + n0 + pn];
    }

    // ---- step 0: h = 0, z = G[0] ----
    if (active) {
        float iv = g_G[(size_t)pb * ZN + 0 * H_ + n0 + pn];
        float jv = g_G[(size_t)pb * ZN + 1 * H_ + n0 + pn];
        float ov = g_G[(size_t)pb * ZN + 3 * H_ + n0 + pn];
        c_reg = sigf(iv) * tanhf(jv);
        float hv = sigf(ov) * tanhf(c_reg);
        unsigned short hs = __half_as_ushort(__float2half_rn(hv));
        asm volatile("st.global.cg.u16 [%0], %1;"
                     :: "l"((char*)g_h16[1] + hbyte), "h"(hs) : "memory");
    }
    __syncthreads();
    if (tid == 0) st_rel(&g_flags[bid * 32], 1u);
    if (active) __stcs(&out[(size_t)pb * (T_ * H_) + n0 + pn], c_reg);

    const uint4* Wq = (const uint4*)W_s + (size_t)wid * 256;

    for (int t = 1; t < T_; ++t) {
        // ---- prefetch G[t+1] (flag-independent; consumed next iteration) ----
        float gn[4];
        if (active) {
            int tn = (t + 1 < T_) ? t + 1 : T_ - 1;
#pragma unroll
            for (int g = 0; g < 4; ++g)
                gn[g] = g_G[((size_t)tn * B_ + pb) * ZN + g * H_ + n0 + pn];
        }

        // ---- per-warp poll: only this warp's 8 producer blocks ----
        if (lane < 8) {
            const unsigned* fp = &g_flags[(wid * 8 + lane) * 32];
            while (ld_acq(fp) < (unsigned)t) { }
        }
        __syncwarp();

        const uint4* hb = (const uint4*)g_h16[t & 1];
        float acc[2][4][4];
#pragma unroll
        for (int mt = 0; mt < 2; ++mt)
#pragma unroll
            for (int nt = 0; nt < 4; ++nt)
#pragma unroll
                for (int e = 0; e < 4; ++e) acc[mt][nt][e] = 0.0f;

#pragma unroll
        for (int kk = 0; kk < 4; ++kk) {
            int c16 = wid * 4 + kk;
            uint4 b0 = Wq[kk * 64 + lane];        // nt0, nt1 fragments
            uint4 b1 = Wq[kk * 64 + 32 + lane];   // nt2, nt3 fragments
            uint32_t a[2][4];
#pragma unroll
            for (int mt = 0; mt < 2; ++mt) {
                uint4 v = __ldcg(&hb[(c16 * 2 + mt) * 32 + lane]);
                a[mt][0] = v.x; a[mt][1] = v.y; a[mt][2] = v.z; a[mt][3] = v.w;
            }
#pragma unroll
            for (int mt = 0; mt < 2; ++mt) {
                mma_f16(acc[mt][0], a[mt], b0.x, b0.y);
                mma_f16(acc[mt][1], a[mt], b0.z, b0.w);
                mma_f16(acc[mt][2], a[mt], b1.x, b1.y);
                mma_f16(acc[mt][3], a[mt], b1.z, b1.w);
            }
        }

        // ---- store per-warp partials ----
#pragma unroll
        for (int mt = 0; mt < 2; ++mt) {
#pragma unroll
            for (int nt = 0; nt < 4; ++nt) {
                int row = mt * 16 + g4;
                int col = nt * 8 + 2 * l4;
                *(float2*)&red[wid * (32 * RED_S) + row * RED_S + col] =
                    make_float2(acc[mt][nt][0], acc[mt][nt][1]);
                *(float2*)&red[wid * (32 * RED_S) + (row + 8) * RED_S + col] =
                    make_float2(acc[mt][nt][2], acc[mt][nt][3]);
            }
        }
        __syncthreads();

        // ---- merged reduce (16 partials) + gates + h store ----
        if (active) {
            float z[4];
#pragma unroll
            for (int g = 0; g < 4; ++g) {
                float s = gq[g];
#pragma unroll
                for (int w = 0; w < 16; ++w)
                    s += red[w * (32 * RED_S) + pb * RED_S + g * 8 + pn];
                z[g] = s;
            }
            c_reg = sigf(z[2] + 1.0f) * c_reg + sigf(z[0]) * tanhf(z[1]);
            float hv = sigf(z[3]) * tanhf(c_reg);
            unsigned short hs = __half_as_ushort(__float2half_rn(hv));
            asm volatile("st.global.cg.u16 [%0], %1;"
                         :: "l"((char*)g_h16[(t + 1) & 1] + hbyte), "h"(hs) : "memory");
        }
        __syncthreads();
        if (tid == 0) st_rel(&g_flags[bid * 32], (unsigned)(t + 1));
        if (active) __stcs(&out[(size_t)pb * (T_ * H_) + (size_t)t * H_ + n0 + pn], c_reg);

#pragma unroll
        for (int g = 0; g < 4; ++g) gq[g] = gn[g];
    }

    // ---- reset flags for deterministic graph replay ----
    __syncthreads();
    if (tid == 0) atomicAdd(&g_done, 1u);
    if (bid == 0) {
        if (tid == 0) {
            while (*(volatile unsigned*)&g_done < (unsigned)NBLK) { }
        }
        __syncthreads();
        if (tid < NBLK) g_flags[tid * 32] = 0u;
        __syncthreads();
        if (tid == 0) { __threadfence(); g_done = 0u; }
    }
}

// ---------------- launch ----------------
extern "C" void kernel_launch(void* const* d_in, const int* in_sizes, int n_in,
                              void* d_out, int out_size) {
    (void)in_sizes; (void)n_in; (void)out_size;
    const float* x    = (const float*)d_in[0];
    const float* kern = (const float*)d_in[2];
    const float* bias = (const float*)d_in[3];
    float* out = (float*)d_out;

    const int smem1 = 3 * 256 * ST1 * 4;                 // 73728 B
    const int smem2 = (16384 + 16 * 32 * RED_S) * 4;     // 147456 B
    cudaFuncSetAttribute(gemm_xw_tc, cudaFuncAttributeMaxDynamicSharedMemorySize, smem1);
    cudaFuncSetAttribute(lstm_seq_tc, cudaFuncAttributeMaxDynamicSharedMemorySize, smem2);

    repack_x<<<dim3(32, 128), 256>>>(x);
    repack_w<<<dim3(32, 32), 256>>>(kern);
    gemm_xw_tc<<<dim3(32, 128), P1T, smem1>>>(bias);
    lstm_seq_tc<<<NBLK, NT2, smem2>>>(kern, out);
}